// round 10
// baseline (speedup 1.0000x reference)
#include <cuda_runtime.h>
#include <math.h>

#define IDIM 128
#define HDIM 1024
#define CDIM 256
#define NIT  4
#define NTOK 2048
#define G    4            // tokens per block (ONE warp per token; warps 4-7 = MLP2 crew)
#define NT   256          // threads per block
#define NBLK (NTOK / G)   // 512 blocks
#define IGNORE_OUT 10000.0f
#define FULLMASK 0xffffffffu

// ---- device scratch (no allocations allowed) ----
__device__ float g_w1t[IDIM * HDIM];   // w1t[d*HDIM + h] = w1[h*IDIM + d]
__device__ float g_w2t[HDIM * IDIM];   // w2t[k*IDIM + o] = w2[o*HDIM + k]
__device__ float g_partS[NBLK];
__device__ int   g_partC[NBLK];
__device__ unsigned int g_ticket;      // zero-init; reset by last block each replay

// ================= merged weight transpose (coalesced tiled) =================
__global__ __launch_bounds__(256) void transpose_both(const float* __restrict__ w1,
                                                      const float* __restrict__ w2)
{
    __shared__ float tile[32][33];
    int tx = threadIdx.x, ty = threadIdx.y;
    int b = blockIdx.x;
    if (b < 128) {
        int bx = b & 3, by = b >> 2;                 // 4 x 32 tiles over (IDIM, HDIM)
        int c0 = bx * 32, r0 = by * 32;              // src HDIM x IDIM
        #pragma unroll
        for (int i = 0; i < 32; i += 8)
            tile[ty + i][tx] = w1[(r0 + ty + i) * IDIM + c0 + tx];
        __syncthreads();
        #pragma unroll
        for (int i = 0; i < 32; i += 8)
            g_w1t[(c0 + ty + i) * HDIM + r0 + tx] = tile[tx][ty + i];
    } else {
        int bb = b - 128;
        int bx = bb & 31, by = bb >> 5;              // 32 x 4 tiles over (HDIM, IDIM)
        int c0 = bx * 32, r0 = by * 32;              // src IDIM x HDIM
        #pragma unroll
        for (int i = 0; i < 32; i += 8)
            tile[ty + i][tx] = w2[(r0 + ty + i) * HDIM + c0 + tx];
        __syncthreads();
        #pragma unroll
        for (int i = 0; i < 32; i += 8)
            g_w2t[(c0 + ty + i) * IDIM + r0 + tx] = tile[tx][ty + i];
    }
}

// ================= fused forward =================
__global__ __launch_bounds__(NT, 4)
void fwd_kernel(const float* __restrict__ x,  const float* __restrict__ y,
                const float* __restrict__ b1, const float* __restrict__ b2,
                float* __restrict__ out)
{
    __shared__ __align__(16) float sxp[G][384];       // zero-padded x_res (pad 127 each side)
    __shared__ __align__(16) float sy [G][132];       // y_res (padded)
    __shared__ __align__(16) float sxa[G][132];       // x_attn (padded)
    __shared__ __align__(16) float sh [G][260];       // h (active block, padded)
    __shared__ __align__(16) float sP [G][132];       // prefix sums of x^2 (129 used)
    __shared__ unsigned char smsk[G][128];            // seq_mask from ORIGINAL y
    __shared__ float redf[8];
    __shared__ int   redi[8];
    __shared__ int   sIsLast;

    const int tid  = threadIdx.x;
    const int blk  = blockIdx.x;
    const int tok0 = blk * G;
    const int lane = tid & 31;
    const int wid  = tid >> 5;        // 8 warps; warps 0-3 own tokens 0-3

    // ---- zero sxp (pads) + load y/mask + count ----
    for (int k = tid; k < G * 384; k += NT) sxp[k / 384][k % 384] = 0.f;

    int cnt = 0;
    #pragma unroll
    for (int q = 0; q < 2; q++) {
        int k = tid + q * NT;                 // 0..511 over (g,d)
        int g = k >> 7, d = k & 127;
        float yv = y[(tok0 + g) * IDIM + d];
        sy[g][d] = yv;
        unsigned char m = (yv == IGNORE_OUT) ? 1 : 0;
        smsk[g][d] = m;
        cnt += 1 - (int)m;
    }
    for (int o = 16; o > 0; o >>= 1) cnt += __shfl_xor_sync(FULLMASK, cnt, o);
    if (lane == 0) redi[wid] = cnt;

    // token warps hold x_res in registers
    float xr[4] = {0.f, 0.f, 0.f, 0.f};
    if (wid < 4) {
        #pragma unroll
        for (int k = 0; k < 4; k++)
            xr[k] = x[(tok0 + wid) * IDIM + k * 32 + lane];
    }

    __syncthreads();
    if (tid == 0) {
        int c = 0;
        for (int w = 0; w < 8; w++) c += redi[w];
        g_partC[blk] = c;
    }

    // MLP1 mapping (all 8 warps): 4 channels x 1 token per thread
    const int m1_g  = tid & 3;             // token
    const int m1_tc = tid >> 2;            // channel group (4 ch): 0..63
    // MLP2 mapping (warps 4-7 only): 4 outputs x 1 token, full K
    const int u     = (tid >= 128) ? (tid - 128) : 0;
    const int m2_og = u >> 2;              // output group (4 out): 0..31
    const int m2_g  = u & 3;               // token
    const float4 b2v = *(const float4*)(b2 + m2_og * 4);

    // prologue: token warps publish xp + prefix sums (iteration 0 inputs)
    if (wid < 4) {
        float* xp = sxp[wid];
        float* Pp = sP[wid];
        #pragma unroll
        for (int k = 0; k < 4; k++) xp[127 + k * 32 + lane] = xr[k];
        float run = 0.f;
        #pragma unroll
        for (int k = 0; k < 4; k++) {
            float v = xr[k] * xr[k];
            #pragma unroll
            for (int o = 1; o < 32; o <<= 1) {
                float n = __shfl_up_sync(FULLMASK, v, o);
                if (lane >= o) v += n;
            }
            Pp[1 + k * 32 + lane] = run + v;
            run += __shfl_sync(FULLMASK, v, 31);
        }
        if (lane == 0) Pp[0] = 0.f;
    }

    float lossAcc = 0.f;

    for (int it = 0; it < NIT; ++it) {
        __syncthreads();   // BAR-D: sy (prev epilogue), xp, sP visible

        // ============ token warps: corr + argmax + softmax + xres ============
        if (wid < 4) {
            float* xp = sxp[wid];
            float* Pp = sP[wid];
            float* yp = sy[wid];
            const float4* yv = (const float4*)(yp);

            float bv = -INFINITY; int bi = 0;
            #pragma unroll
            for (int h = 0; h < 2; h++) {
                // sliding float4 window: lane owns shifts s = 4*lane + r + 128*h
                float a0 = 0.f, a1 = 0.f, a2 = 0.f, a3 = 0.f;
                const float4* xv = (const float4*)(xp) + lane + 32 * h;
                float4 cur = xv[0];
                #pragma unroll 8
                for (int t = 0; t < 32; t++) {
                    float4 nxt = xv[t + 1];
                    float4 y4  = yv[t];
                    a0 = fmaf(cur.x, y4.x, a0); a0 = fmaf(cur.y, y4.y, a0);
                    a0 = fmaf(cur.z, y4.z, a0); a0 = fmaf(cur.w, y4.w, a0);
                    a1 = fmaf(cur.y, y4.x, a1); a1 = fmaf(cur.z, y4.y, a1);
                    a1 = fmaf(cur.w, y4.z, a1); a1 = fmaf(nxt.x, y4.w, a1);
                    a2 = fmaf(cur.z, y4.x, a2); a2 = fmaf(cur.w, y4.y, a2);
                    a2 = fmaf(nxt.x, y4.z, a2); a2 = fmaf(nxt.y, y4.w, a2);
                    a3 = fmaf(cur.w, y4.x, a3); a3 = fmaf(nxt.x, y4.y, a3);
                    a3 = fmaf(nxt.y, y4.z, a3); a3 = fmaf(nxt.z, y4.w, a3);
                    cur = nxt;
                }
                const int s0 = 4 * lane + 128 * h;
                float num[4] = {a0, a1, a2, a3};
                #pragma unroll
                for (int r = 0; r < 4; r++) {
                    int s = s0 + r;
                    float sim;
                    if (s < 255) {
                        int lo = s - 127; if (lo < 0) lo = 0;
                        int hi = s;       if (hi > 127) hi = 127;
                        float dxv = Pp[hi + 1] - Pp[lo];
                        sim = (dxv > 0.f) ? num[r] * rsqrtf(dxv) : 0.f;
                    } else sim = -INFINITY;
                    if (sim > bv) { bv = sim; bi = s; }  // ascending s keeps first max
                }
            }
            #pragma unroll
            for (int o = 16; o > 0; o >>= 1) {
                float ov = __shfl_xor_sync(FULLMASK, bv, o);
                int   oi = __shfl_xor_sync(FULLMASK, bi, o);
                if (ov > bv || (ov == bv && oi < bi)) { bv = ov; bi = oi; }
            }

            // softmax attention + x_attn (warp-local)
            float xa[4], e[4];
            float m = -INFINITY;
            #pragma unroll
            for (int k = 0; k < 4; k++) {
                int d = k * 32 + lane;
                xa[k] = xp[bi + d];                    // kpt[bi][d]
                e[k]  = xa[k] * yp[d];
                m = fmaxf(m, e[k]);
            }
            #pragma unroll
            for (int o = 16; o > 0; o >>= 1) m = fmaxf(m, __shfl_xor_sync(FULLMASK, m, o));
            float se = 0.f;
            #pragma unroll
            for (int k = 0; k < 4; k++) { e[k] = expf(e[k] - m); se += e[k]; }
            #pragma unroll
            for (int o = 16; o > 0; o >>= 1) se += __shfl_xor_sync(FULLMASK, se, o);
            float inv = 1.f / se;
            #pragma unroll
            for (int k = 0; k < 4; k++) {
                int d = k * 32 + lane;
                sxa[wid][d] = xa[k] * (e[k] * inv);
            }
            __syncwarp();   // sxa cross-lane reads below

            // x_res update + republish xp + prefix sums for NEXT iteration
            const int off = bi - 127;
            #pragma unroll
            for (int k = 0; k < 4; k++) {
                int d = k * 32 + lane;
                int q = d - off;
                float xe = (q >= 0 && q < 128) ? sxa[wid][q] : 0.f;
                xr[k] -= xe;
                xp[127 + d] = xr[k];
            }
            float run = 0.f;
            #pragma unroll
            for (int k = 0; k < 4; k++) {
                float v = xr[k] * xr[k];
                #pragma unroll
                for (int o = 1; o < 32; o <<= 1) {
                    float n = __shfl_up_sync(FULLMASK, v, o);
                    if (lane >= o) v += n;
                }
                Pp[1 + k * 32 + lane] = run + v;
                run += __shfl_sync(FULLMASK, v, 31);
            }
            if (lane == 0) Pp[0] = 0.f;
        }
        __syncthreads();   // BAR-A: sxa visible

        // ============ MLP layer 1 (all 8 warps): 4 ch x 1 token per thread ====
        {
            const float*  wp  = g_w1t + it * CDIM + m1_tc * 4;
            const float4* apv = (const float4*)sxa[m1_g];
            float c0 = 0.f, c1 = 0.f, c2 = 0.f, c3 = 0.f;
            #pragma unroll 4
            for (int d4 = 0; d4 < 32; d4++) {
                float4 a  = apv[d4];
                const float* w = wp + (d4 * 4) * HDIM;
                float4 w0 = *(const float4*)(w);
                float4 w1v = *(const float4*)(w + HDIM);
                float4 w2v = *(const float4*)(w + 2 * HDIM);
                float4 w3v = *(const float4*)(w + 3 * HDIM);
                c0 = fmaf(w0.x, a.x, c0); c1 = fmaf(w0.y, a.x, c1);
                c2 = fmaf(w0.z, a.x, c2); c3 = fmaf(w0.w, a.x, c3);
                c0 = fmaf(w1v.x, a.y, c0); c1 = fmaf(w1v.y, a.y, c1);
                c2 = fmaf(w1v.z, a.y, c2); c3 = fmaf(w1v.w, a.y, c3);
                c0 = fmaf(w2v.x, a.z, c0); c1 = fmaf(w2v.y, a.z, c1);
                c2 = fmaf(w2v.z, a.z, c2); c3 = fmaf(w2v.w, a.z, c3);
                c0 = fmaf(w3v.x, a.w, c0); c1 = fmaf(w3v.y, a.w, c1);
                c2 = fmaf(w3v.z, a.w, c2); c3 = fmaf(w3v.w, a.w, c3);
            }
            float4 bb = *(const float4*)(b1 + it * CDIM + m1_tc * 4);
            *(float4*)&sh[m1_g][m1_tc * 4] =
                make_float4(c0 + bb.x, c1 + bb.y, c2 + bb.z, c3 + bb.w);
        }
        __syncthreads();   // BAR-B: sh visible

        // ============ MLP layer 2 (warps 4-7, full K) + loss + sy update ======
        if (wid >= 4) {
            const float*  wp  = g_w2t + (it * CDIM) * IDIM + m2_og * 4;
            const float4* hpv = (const float4*)(sh[m2_g]);
            float c0 = 0.f, c1 = 0.f, c2 = 0.f, c3 = 0.f;
            #pragma unroll 4
            for (int k4 = 0; k4 < 64; k4++) {
                float4 h  = hpv[k4];
                const float* w = wp + (k4 * 4) * IDIM;
                float4 w0 = *(const float4*)(w);
                float4 w1v = *(const float4*)(w + IDIM);
                float4 w2v = *(const float4*)(w + 2 * IDIM);
                float4 w3v = *(const float4*)(w + 3 * IDIM);
                c0 = fmaf(w0.x, h.x, c0); c1 = fmaf(w0.y, h.x, c1);
                c2 = fmaf(w0.z, h.x, c2); c3 = fmaf(w0.w, h.x, c3);
                c0 = fmaf(w1v.x, h.y, c0); c1 = fmaf(w1v.y, h.y, c1);
                c2 = fmaf(w1v.z, h.y, c2); c3 = fmaf(w1v.w, h.y, c3);
                c0 = fmaf(w2v.x, h.z, c0); c1 = fmaf(w2v.y, h.z, c1);
                c2 = fmaf(w2v.z, h.z, c2); c3 = fmaf(w2v.w, h.z, c3);
                c0 = fmaf(w3v.x, h.w, c0); c1 = fmaf(w3v.y, h.w, c1);
                c2 = fmaf(w3v.z, h.w, c2); c3 = fmaf(w3v.w, h.w, c3);
            }
            float4 yr = *(const float4*)&sy[m2_g][m2_og * 4];
            const unsigned char* mp = &smsk[m2_g][m2_og * 4];
            float ye0 = c0 + b2v.x, ye1 = c1 + b2v.y;
            float ye2 = c2 + b2v.z, ye3 = c3 + b2v.w;
            float d0 = ye0 - yr.x, d1 = ye1 - yr.y, d2 = ye2 - yr.z, d3 = ye3 - yr.w;
            if (!mp[0]) lossAcc += d0 * d0;
            if (!mp[1]) lossAcc += d1 * d1;
            if (!mp[2]) lossAcc += d2 * d2;
            if (!mp[3]) lossAcc += d3 * d3;
            *(float4*)&sy[m2_g][m2_og * 4] =
                make_float4(yr.x - ye0, yr.y - ye1, yr.z - ye2, yr.w - ye3);
        }
        // loop-top BAR-D orders sy/xp/sP before next-iter reads
    }

    // ---- deterministic per-block loss reduction ----
    for (int o = 16; o > 0; o >>= 1) lossAcc += __shfl_xor_sync(FULLMASK, lossAcc, o);
    __syncthreads();                 // protect redf reuse
    if (lane == 0) redf[wid] = lossAcc;
    __syncthreads();
    if (tid == 0) {
        float s = 0.f;
        for (int w = 0; w < 8; w++) s += redf[w];
        g_partS[blk] = s;
        __threadfence();
        unsigned int t = atomicAdd(&g_ticket, 1u);
        sIsLast = (t == NBLK - 1) ? 1 : 0;
    }
    __syncthreads();

    // ---- last block: fused deterministic finalize ----
    if (sIsLast) {
        __threadfence();
        volatile float* vS = g_partS;
        volatile int*   vC = g_partC;
        float s = vS[tid] + vS[tid + 256];      // NBLK = 512 = 2*NT
        int   c = vC[tid] + vC[tid + 256];
        for (int o = 16; o > 0; o >>= 1) {
            s += __shfl_xor_sync(FULLMASK, s, o);
            c += __shfl_xor_sync(FULLMASK, c, o);
        }
        if (lane == 0) { redf[wid] = s; redi[wid] = c; }
        __syncthreads();
        if (tid == 0) {
            float S = 0.f; int C = 0;
            for (int w = 0; w < 8; w++) { S += redf[w]; C += redi[w]; }
            out[0] = S / (4.0f * (float)C);   // mean over NIT of (sum_sq / denom)
            g_ticket = 0;                     // reset for next graph replay
        }
    }
}

extern "C" void kernel_launch(void* const* d_in, const int* in_sizes, int n_in,
                              void* d_out, int out_size)
{
    const float* x  = (const float*)d_in[0];
    const float* y  = (const float*)d_in[1];
    const float* w1 = (const float*)d_in[2];
    const float* b1 = (const float*)d_in[3];
    const float* w2 = (const float*)d_in[4];
    const float* b2 = (const float*)d_in[5];

    transpose_both<<<256, dim3(32, 8)>>>(w1, w2);
    fwd_kernel<<<NBLK, NT>>>(x, y, b1, b2, (float*)d_out);
}

// round 11
// speedup vs baseline: 1.1351x; 1.1351x over previous
#include <cuda_runtime.h>
#include <math.h>

#define IDIM 128
#define HDIM 1024
#define CDIM 256
#define NIT  4
#define NTOK 2048
#define G    4            // tokens per block (two warps per token)
#define NT   256          // threads per block
#define NBLK (NTOK / G)   // 512 blocks
#define IGNORE_OUT 10000.0f
#define FULLMASK 0xffffffffu

// pair-local named barrier: 64 threads (two warps of one token)
#define PAIR_BAR(tokid) asm volatile("bar.sync %0, 64;" :: "r"((tokid) + 1) : "memory")

// ---- device scratch (no allocations allowed) ----
__device__ float g_w1t[IDIM * HDIM];   // w1t[d*HDIM + h] = w1[h*IDIM + d]
__device__ float g_w2t[HDIM * IDIM];   // w2t[k*IDIM + o] = w2[o*HDIM + k]
__device__ float g_partS[NBLK];
__device__ int   g_partC[NBLK];
__device__ unsigned int g_ticket;      // zero-init; reset by last block each replay

// ================= merged weight transpose (coalesced tiled) =================
__global__ __launch_bounds__(256) void transpose_both(const float* __restrict__ w1,
                                                      const float* __restrict__ w2)
{
    __shared__ float tile[32][33];
    int tx = threadIdx.x, ty = threadIdx.y;
    int b = blockIdx.x;
    if (b < 128) {
        int bx = b & 3, by = b >> 2;                 // 4 x 32 tiles over (IDIM, HDIM)
        int c0 = bx * 32, r0 = by * 32;              // src HDIM x IDIM
        #pragma unroll
        for (int i = 0; i < 32; i += 8)
            tile[ty + i][tx] = w1[(r0 + ty + i) * IDIM + c0 + tx];
        __syncthreads();
        #pragma unroll
        for (int i = 0; i < 32; i += 8)
            g_w1t[(c0 + ty + i) * HDIM + r0 + tx] = tile[tx][ty + i];
    } else {
        int bb = b - 128;
        int bx = bb & 31, by = bb >> 5;              // 32 x 4 tiles over (HDIM, IDIM)
        int c0 = bx * 32, r0 = by * 32;              // src IDIM x HDIM
        #pragma unroll
        for (int i = 0; i < 32; i += 8)
            tile[ty + i][tx] = w2[(r0 + ty + i) * HDIM + c0 + tx];
        __syncthreads();
        #pragma unroll
        for (int i = 0; i < 32; i += 8)
            g_w2t[(c0 + ty + i) * IDIM + r0 + tx] = tile[tx][ty + i];
    }
}

// ================= fused forward =================
__global__ __launch_bounds__(NT, 4)
void fwd_kernel(const float* __restrict__ x,  const float* __restrict__ y,
                const float* __restrict__ b1, const float* __restrict__ b2,
                float* __restrict__ out)
{
    __shared__ __align__(16) float sxp[G][384];       // zero-padded x_res (pad 127 each side)
    __shared__ __align__(16) float sy [G][132];       // y_res (padded)
    __shared__ __align__(16) float sxa[G][132];       // x_attn (padded)
    __shared__ __align__(16) float sh [G][260];       // h (active block, padded)
    __shared__ __align__(16) float sP [G][132];       // prefix sums of x^2 (129 used)
    __shared__ __align__(16) float sye[G][132];       // MLP2 half-1 partials
    __shared__ float s_bv[G][2];                      // per-warp argmax value
    __shared__ int   s_bi[G][2];                      // per-warp argmax index
    __shared__ unsigned char smsk[G][128];            // seq_mask from ORIGINAL y
    __shared__ float redf[8];
    __shared__ int   redi[8];
    __shared__ int   sIsLast;

    const int tid  = threadIdx.x;
    const int blk  = blockIdx.x;
    const int tok0 = blk * G;
    const int lane = tid & 31;
    const int wid  = tid >> 5;        // 8 warps
    const int tok  = wid >> 1;        // token for per-token phases
    const int sub  = wid & 1;         // corr pass: s in [128*sub, 128*sub+128)

    // ---- zero sxp pads + load y/mask + count ----
    for (int k = tid; k < G * 384; k += NT) sxp[k / 384][k % 384] = 0.f;

    int cnt = 0;
    #pragma unroll
    for (int q = 0; q < 2; q++) {
        int k = tid + q * NT;                 // 0..511 over (g,d)
        int g = k >> 7, d = k & 127;
        float yv = y[(tok0 + g) * IDIM + d];
        sy[g][d] = yv;
        unsigned char m = (yv == IGNORE_OUT) ? 1 : 0;
        smsk[g][d] = m;
        cnt += 1 - (int)m;
    }
    for (int o = 16; o > 0; o >>= 1) cnt += __shfl_xor_sync(FULLMASK, cnt, o);
    if (lane == 0) redi[wid] = cnt;

    // x_res registers: BOTH warps of a token pair hold identical copies.
    float xr[4];
    #pragma unroll
    for (int k = 0; k < 4; k++)
        xr[k] = x[(tok0 + tok) * IDIM + k * 32 + lane];

    __syncthreads();
    if (tid == 0) {
        int c = 0;
        for (int w = 0; w < 8; w++) c += redi[w];
        g_partC[blk] = c;
    }

    // MLP mappings
    const int m1_g  = tid & 3;             // token
    const int m1_tc = tid >> 2;            // channel group (4 ch): 0..63
    const int m2_g  = tid & 3;             // token
    const int m2_oc = (tid >> 2) & 31;     // output group (4 out): 0..31
    const int m2_hf = tid >> 7;            // K half

    // bias registers (loop-invariant)
    const float4 b2v = *(const float4*)(b2 + m2_oc * 4);

    // ---- prologue: publish xp + prefix sums for iteration 0 ----
    {
        float* xp = sxp[tok];
        float* Pp = sP[tok];
        if (sub == 1) {
            #pragma unroll
            for (int k = 0; k < 4; k++) xp[127 + k * 32 + lane] = xr[k];
        } else {
            float run = 0.f;
            #pragma unroll
            for (int k = 0; k < 4; k++) {
                float v = xr[k] * xr[k];
                #pragma unroll
                for (int o = 1; o < 32; o <<= 1) {
                    float n = __shfl_up_sync(FULLMASK, v, o);
                    if (lane >= o) v += n;
                }
                Pp[1 + k * 32 + lane] = run + v;
                run += __shfl_sync(FULLMASK, v, 31);
            }
            if (lane == 0) Pp[0] = 0.f;
        }
    }

    float lossAcc = 0.f;

    for (int it = 0; it < NIT; ++it) {
        __syncthreads();   // BAR-TOP: xp/sP publish + prev-iter sy visible

        float* xp = sxp[tok];
        float* Pp = sP[tok];
        float* yp = sy[tok];

        // (1) corr numerators, sliding float4 window.
        //     lane owns shifts s = 4*lane + r + 128*sub  (r = 0..3)
        float a0 = 0.f, a1 = 0.f, a2 = 0.f, a3 = 0.f;
        {
            const float4* xv = (const float4*)(xp) + lane + 32 * sub;  // chunk base s/4
            const float4* yv = (const float4*)(yp);
            float4 cur = xv[0];
            #pragma unroll 8
            for (int t = 0; t < 32; t++) {
                float4 nxt = xv[t + 1];
                float4 y4  = yv[t];
                a0 = fmaf(cur.x, y4.x, a0); a0 = fmaf(cur.y, y4.y, a0);
                a0 = fmaf(cur.z, y4.z, a0); a0 = fmaf(cur.w, y4.w, a0);
                a1 = fmaf(cur.y, y4.x, a1); a1 = fmaf(cur.z, y4.y, a1);
                a1 = fmaf(cur.w, y4.z, a1); a1 = fmaf(nxt.x, y4.w, a1);
                a2 = fmaf(cur.z, y4.x, a2); a2 = fmaf(cur.w, y4.y, a2);
                a2 = fmaf(nxt.x, y4.z, a2); a2 = fmaf(nxt.y, y4.w, a2);
                a3 = fmaf(cur.w, y4.x, a3); a3 = fmaf(nxt.x, y4.y, a3);
                a3 = fmaf(nxt.y, y4.z, a3); a3 = fmaf(nxt.z, y4.w, a3);
                cur = nxt;
            }
        }

        // (2) per-warp sim + first-max argmax over its 128 shifts
        {
            const int s0 = 4 * lane + 128 * sub;
            float num[4] = {a0, a1, a2, a3};
            float bv = -INFINITY; int bi = 0;
            #pragma unroll
            for (int r = 0; r < 4; r++) {
                int s = s0 + r;
                float sim;
                if (s < 255) {
                    int lo = s - 127; if (lo < 0) lo = 0;
                    int hi = s;       if (hi > 127) hi = 127;
                    float dxv = Pp[hi + 1] - Pp[lo];
                    sim = (dxv > 0.f) ? num[r] * rsqrtf(dxv) : 0.f;
                } else sim = -INFINITY;
                if (sim > bv) { bv = sim; bi = s; }   // ascending s keeps first max
            }
            #pragma unroll
            for (int o = 16; o > 0; o >>= 1) {
                float ov = __shfl_xor_sync(FULLMASK, bv, o);
                int   oi = __shfl_xor_sync(FULLMASK, bi, o);
                if (ov > bv || (ov == bv && oi < bi)) { bv = ov; bi = oi; }
            }
            if (lane == 0) { s_bv[tok][sub] = bv; s_bi[tok][sub] = bi; }
        }
        PAIR_BAR(tok);     // pair-local: per-warp bests visible

        // (3) BOTH warps: combine, softmax attention, x_attn (redundant identical)
        int bi;
        {
            float v0 = s_bv[tok][0]; int i0 = s_bi[tok][0];
            float v1 = s_bv[tok][1]; int i1 = s_bi[tok][1];
            bi = (v1 > v0 || (v1 == v0 && i1 < i0)) ? i1 : i0;

            float xa[4], e[4];
            float m = -INFINITY;
            #pragma unroll
            for (int k = 0; k < 4; k++) {
                int d = k * 32 + lane;
                xa[k] = xp[bi + d];                    // kpt[bi][d]
                e[k]  = xa[k] * yp[d];
                m = fmaxf(m, e[k]);
            }
            #pragma unroll
            for (int o = 16; o > 0; o >>= 1) m = fmaxf(m, __shfl_xor_sync(FULLMASK, m, o));
            float se = 0.f;
            #pragma unroll
            for (int k = 0; k < 4; k++) { e[k] = __expf(e[k] - m); se += e[k]; }
            #pragma unroll
            for (int o = 16; o > 0; o >>= 1) se += __shfl_xor_sync(FULLMASK, se, o);
            float inv = 1.f / se;
            #pragma unroll
            for (int k = 0; k < 4; k++) {
                int d = k * 32 + lane;
                sxa[tok][d] = xa[k] * (e[k] * inv);    // both warps write same values
            }
        }
        __syncwarp();       // own sxa writes visible to own cross-lane reads

        // (4) x_res update (reads own-warp sxa copies)
        {
            const int off = bi - 127;
            #pragma unroll
            for (int k = 0; k < 4; k++) {
                int d = k * 32 + lane;
                int q = d - off;
                float xe = (q >= 0 && q < 128) ? sxa[tok][q] : 0.f;
                xr[k] -= xe;
            }
        }
        PAIR_BAR(tok);      // pair-local: xp softmax-reads done before republish

        // (5) republish xp (sub1) + prefix scan (sub0) for NEXT iteration
        if (sub == 1) {
            #pragma unroll
            for (int k = 0; k < 4; k++) xp[127 + k * 32 + lane] = xr[k];
        } else {
            float run = 0.f;
            #pragma unroll
            for (int k = 0; k < 4; k++) {
                float v = xr[k] * xr[k];
                #pragma unroll
                for (int o = 1; o < 32; o <<= 1) {
                    float n = __shfl_up_sync(FULLMASK, v, o);
                    if (lane >= o) v += n;
                }
                Pp[1 + k * 32 + lane] = run + v;
                run += __shfl_sync(FULLMASK, v, 31);
            }
            if (lane == 0) Pp[0] = 0.f;
        }
        __syncthreads();   // BAR-A: sxa visible for MLP1

        // (6) MLP layer 1: 4 channels x 1 token per thread, d-blocks of 4
        {
            const float*  wp  = g_w1t + it * CDIM + m1_tc * 4;
            const float4* apv = (const float4*)sxa[m1_g];
            float c0 = 0.f, c1 = 0.f, c2 = 0.f, c3 = 0.f;
            #pragma unroll 4
            for (int d4 = 0; d4 < 32; d4++) {
                float4 a  = apv[d4];
                const float* w = wp + (d4 * 4) * HDIM;
                float4 w0 = *(const float4*)(w);
                float4 w1v = *(const float4*)(w + HDIM);
                float4 w2v = *(const float4*)(w + 2 * HDIM);
                float4 w3v = *(const float4*)(w + 3 * HDIM);
                c0 = fmaf(w0.x, a.x, c0); c1 = fmaf(w0.y, a.x, c1);
                c2 = fmaf(w0.z, a.x, c2); c3 = fmaf(w0.w, a.x, c3);
                c0 = fmaf(w1v.x, a.y, c0); c1 = fmaf(w1v.y, a.y, c1);
                c2 = fmaf(w1v.z, a.y, c2); c3 = fmaf(w1v.w, a.y, c3);
                c0 = fmaf(w2v.x, a.z, c0); c1 = fmaf(w2v.y, a.z, c1);
                c2 = fmaf(w2v.z, a.z, c2); c3 = fmaf(w2v.w, a.z, c3);
                c0 = fmaf(w3v.x, a.w, c0); c1 = fmaf(w3v.y, a.w, c1);
                c2 = fmaf(w3v.z, a.w, c2); c3 = fmaf(w3v.w, a.w, c3);
            }
            float4 bb = *(const float4*)(b1 + it * CDIM + m1_tc * 4);
            *(float4*)&sh[m1_g][m1_tc * 4] =
                make_float4(c0 + bb.x, c1 + bb.y, c2 + bb.z, c3 + bb.w);
        }
        __syncthreads();   // BAR-B: sh visible

        // (7) MLP layer 2 (half-K per thread) + loss + y_res update
        {
            const float*  wp  = g_w2t + (it * CDIM + m2_hf * 128) * IDIM + m2_oc * 4;
            const float4* hpv = (const float4*)(&sh[m2_g][m2_hf * 128]);
            float c0 = 0.f, c1 = 0.f, c2 = 0.f, c3 = 0.f;
            #pragma unroll 4
            for (int k4 = 0; k4 < 32; k4++) {
                float4 h  = hpv[k4];
                const float* w = wp + (k4 * 4) * IDIM;
                float4 w0 = *(const float4*)(w);
                float4 w1v = *(const float4*)(w + IDIM);
                float4 w2v = *(const float4*)(w + 2 * IDIM);
                float4 w3v = *(const float4*)(w + 3 * IDIM);
                c0 = fmaf(w0.x, h.x, c0); c1 = fmaf(w0.y, h.x, c1);
                c2 = fmaf(w0.z, h.x, c2); c3 = fmaf(w0.w, h.x, c3);
                c0 = fmaf(w1v.x, h.y, c0); c1 = fmaf(w1v.y, h.y, c1);
                c2 = fmaf(w1v.z, h.y, c2); c3 = fmaf(w1v.w, h.y, c3);
                c0 = fmaf(w2v.x, h.z, c0); c1 = fmaf(w2v.y, h.z, c1);
                c2 = fmaf(w2v.z, h.z, c2); c3 = fmaf(w2v.w, h.z, c3);
                c0 = fmaf(w3v.x, h.w, c0); c1 = fmaf(w3v.y, h.w, c1);
                c2 = fmaf(w3v.z, h.w, c2); c3 = fmaf(w3v.w, h.w, c3);
            }
            // hoist pre-barrier operands for the epilogue
            float4 yr = *(const float4*)&sy[m2_g][m2_oc * 4];
            const unsigned char* mp = &smsk[m2_g][m2_oc * 4];
            unsigned char mk0 = mp[0], mk1 = mp[1], mk2 = mp[2], mk3 = mp[3];
            if (m2_hf == 1)
                *(float4*)&sye[m2_g][m2_oc * 4] = make_float4(c0, c1, c2, c3);
            __syncthreads();   // BAR-C: partials visible
            if (m2_hf == 0) {
                float4 pb = *(const float4*)&sye[m2_g][m2_oc * 4];
                float ye0 = c0 + pb.x + b2v.x;
                float ye1 = c1 + pb.y + b2v.y;
                float ye2 = c2 + pb.z + b2v.z;
                float ye3 = c3 + pb.w + b2v.w;
                float d0 = ye0 - yr.x, d1 = ye1 - yr.y, d2 = ye2 - yr.z, d3 = ye3 - yr.w;
                if (!mk0) lossAcc += d0 * d0;
                if (!mk1) lossAcc += d1 * d1;
                if (!mk2) lossAcc += d2 * d2;
                if (!mk3) lossAcc += d3 * d3;
                *(float4*)&sy[m2_g][m2_oc * 4] =
                    make_float4(yr.x - ye0, yr.y - ye1, yr.z - ye2, yr.w - ye3);
            }
        }
        // loop-top BAR-TOP orders the sy writes before next-iter corr reads
    }

    // ---- deterministic per-block loss reduction ----
    for (int o = 16; o > 0; o >>= 1) lossAcc += __shfl_xor_sync(FULLMASK, lossAcc, o);
    __syncthreads();                 // protect redf reuse
    if (lane == 0) redf[wid] = lossAcc;
    __syncthreads();
    if (tid == 0) {
        float s = 0.f;
        for (int w = 0; w < 8; w++) s += redf[w];
        g_partS[blk] = s;
        __threadfence();
        unsigned int t = atomicAdd(&g_ticket, 1u);
        sIsLast = (t == NBLK - 1) ? 1 : 0;
    }
    __syncthreads();

    // ---- last block: fused deterministic finalize ----
    if (sIsLast) {
        __threadfence();
        volatile float* vS = g_partS;
        volatile int*   vC = g_partC;
        float s = vS[tid] + vS[tid + 256];      // NBLK = 512 = 2*NT
        int   c = vC[tid] + vC[tid + 256];
        for (int o = 16; o > 0; o >>= 1) {
            s += __shfl_xor_sync(FULLMASK, s, o);
            c += __shfl_xor_sync(FULLMASK, c, o);
        }
        if (lane == 0) { redf[wid] = s; redi[wid] = c; }
        __syncthreads();
        if (tid == 0) {
            float S = 0.f; int C = 0;
            for (int w = 0; w < 8; w++) { S += redf[w]; C += redi[w]; }
            out[0] = S / (4.0f * (float)C);   // mean over NIT of (sum_sq / denom)
            g_ticket = 0;                     // reset for next graph replay
        }
    }
}

extern "C" void kernel_launch(void* const* d_in, const int* in_sizes, int n_in,
                              void* d_out, int out_size)
{
    const float* x  = (const float*)d_in[0];
    const float* y  = (const float*)d_in[1];
    const float* w1 = (const float*)d_in[2];
    const float* b1 = (const float*)d_in[3];
    const float* w2 = (const float*)d_in[4];
    const float* b2 = (const float*)d_in[5];

    transpose_both<<<256, dim3(32, 8)>>>(w1, w2);
    fwd_kernel<<<NBLK, NT>>>(x, y, b1, b2, (float*)d_out);
}

// round 12
// speedup vs baseline: 1.9508x; 1.7186x over previous
#include <cuda_runtime.h>
#include <math.h>

#define IDIM 128
#define HDIM 1024
#define CDIM 256
#define NIT  4
#define NTOK 2048
#define G    4            // tokens per block (two warps per token)
#define NT   256          // threads per block
#define NBLK (NTOK / G)   // 512 blocks
#define IGNORE_OUT 10000.0f
#define FULLMASK 0xffffffffu

// pair-local named barrier: 64 threads (two warps of one token)
#define PAIR_BAR(tokid) asm volatile("bar.sync %0, 64;" :: "r"((tokid) + 1) : "memory")

// ---- device scratch (no allocations allowed) ----
__device__ float g_wf[NIT * IDIM * IDIM];  // fused W: [it][d][o], o-contiguous
__device__ float g_bf[NIT * IDIM];         // fused bias: [it][o]
__device__ float g_partS[NBLK];
__device__ int   g_partC[NBLK];
__device__ unsigned int g_ticket;          // zero-init; reset by last block each replay

// ================= prologue: fused-weight GEMM =================
// Wf[it][d][o] = sum_{c<256} w1[it*256+c][d] * w2[o][it*256+c]
// bf[it][o]    = sum_{c<256} b1[it*256+c]    * w2[o][it*256+c] + b2[o]
__global__ __launch_bounds__(256) void gemm_fuse(const float* __restrict__ w1,
                                                 const float* __restrict__ w2,
                                                 const float* __restrict__ b1,
                                                 const float* __restrict__ b2)
{
    __shared__ float As[32][33];   // [c][d_local]
    __shared__ float Bs[32][33];   // [c][o_local]
    const int b  = blockIdx.x;     // 64 blocks: it(4) x dt(4) x ot(4)
    const int it = b >> 4;
    const int dt = (b >> 2) & 3;
    const int ot = b & 3;
    const int tx = threadIdx.x;    // 0..31 (o_local / col)
    const int ty = threadIdx.y;    // 0..7

    float acc[4] = {0.f, 0.f, 0.f, 0.f};
    float bacc = 0.f;

    for (int kc = 0; kc < 8; kc++) {
        #pragma unroll
        for (int i = 0; i < 4; i++) {
            int c = ty + 8 * i;
            As[c][tx] = w1[(it * CDIM + kc * 32 + c) * IDIM + dt * 32 + tx];
            Bs[tx][c] = w2[(ot * 32 + c) * HDIM + it * CDIM + kc * 32 + tx];
        }
        __syncthreads();
        #pragma unroll 8
        for (int c = 0; c < 32; c++) {
            float bv = Bs[c][tx];
            #pragma unroll
            for (int i = 0; i < 4; i++)
                acc[i] = fmaf(As[c][ty + 8 * i], bv, acc[i]);
        }
        if (dt == 0 && ty == 0) {
            #pragma unroll 8
            for (int c = 0; c < 32; c++)
                bacc = fmaf(b1[it * CDIM + kc * 32 + c], Bs[c][tx], bacc);
        }
        __syncthreads();
    }
    #pragma unroll
    for (int i = 0; i < 4; i++)
        g_wf[(it * IDIM + dt * 32 + ty + 8 * i) * IDIM + ot * 32 + tx] = acc[i];
    if (dt == 0 && ty == 0)
        g_bf[it * IDIM + ot * 32 + tx] = bacc + b2[ot * 32 + tx];
}

// ================= fused forward =================
__global__ __launch_bounds__(NT, 4)
void fwd_kernel(const float* __restrict__ x,  const float* __restrict__ y,
                float* __restrict__ out)
{
    __shared__ __align__(16) float sxp[G][384];       // zero-padded x_res (pad 127 each side)
    __shared__ __align__(16) float sy [G][132];       // y_res (padded)
    __shared__ __align__(16) float sxa[G][132];       // x_attn (padded)
    __shared__ __align__(16) float sP [G][132];       // prefix sums of x^2 (129 used)
    __shared__ __align__(16) float sye[G][132];       // fused-MLP half-1 partials
    __shared__ float s_bv[G][2];                      // per-warp argmax value
    __shared__ int   s_bi[G][2];                      // per-warp argmax index
    __shared__ unsigned char smsk[G][128];            // seq_mask from ORIGINAL y
    __shared__ float redf[8];
    __shared__ int   redi[8];
    __shared__ int   sIsLast;

    const int tid  = threadIdx.x;
    const int blk  = blockIdx.x;
    const int tok0 = blk * G;
    const int lane = tid & 31;
    const int wid  = tid >> 5;        // 8 warps
    const int tok  = wid >> 1;        // token for per-token phases
    const int sub  = wid & 1;         // corr pass: s in [128*sub, 128*sub+128)

    // ---- zero sxp pads + load y/mask + count ----
    for (int k = tid; k < G * 384; k += NT) sxp[k / 384][k % 384] = 0.f;

    int cnt = 0;
    #pragma unroll
    for (int q = 0; q < 2; q++) {
        int k = tid + q * NT;                 // 0..511 over (g,d)
        int g = k >> 7, d = k & 127;
        float yv = y[(tok0 + g) * IDIM + d];
        sy[g][d] = yv;
        unsigned char m = (yv == IGNORE_OUT) ? 1 : 0;
        smsk[g][d] = m;
        cnt += 1 - (int)m;
    }
    for (int o = 16; o > 0; o >>= 1) cnt += __shfl_xor_sync(FULLMASK, cnt, o);
    if (lane == 0) redi[wid] = cnt;

    // x_res registers: BOTH warps of a token pair hold identical copies.
    float xr[4];
    #pragma unroll
    for (int k = 0; k < 4; k++)
        xr[k] = x[(tok0 + tok) * IDIM + k * 32 + lane];

    __syncthreads();
    if (tid == 0) {
        int c = 0;
        for (int w = 0; w < 8; w++) c += redi[w];
        g_partC[blk] = c;
    }

    // fused-MLP mapping: 4 outputs x 1 token x half-d per thread
    const int m2_g  = tid & 3;             // token
    const int m2_oc = (tid >> 2) & 31;     // output group (4 out): 0..31
    const int m2_hf = tid >> 7;            // d half

    // ---- prologue: publish xp + prefix sums for iteration 0 ----
    {
        float* xp = sxp[tok];
        float* Pp = sP[tok];
        if (sub == 1) {
            #pragma unroll
            for (int k = 0; k < 4; k++) xp[127 + k * 32 + lane] = xr[k];
        } else {
            float run = 0.f;
            #pragma unroll
            for (int k = 0; k < 4; k++) {
                float v = xr[k] * xr[k];
                #pragma unroll
                for (int o = 1; o < 32; o <<= 1) {
                    float n = __shfl_up_sync(FULLMASK, v, o);
                    if (lane >= o) v += n;
                }
                Pp[1 + k * 32 + lane] = run + v;
                run += __shfl_sync(FULLMASK, v, 31);
            }
            if (lane == 0) Pp[0] = 0.f;
        }
    }

    float lossAcc = 0.f;

    for (int it = 0; it < NIT; ++it) {
        __syncthreads();   // BAR-TOP: xp/sP publish + prev-iter sy visible

        float* xp = sxp[tok];
        float* Pp = sP[tok];
        float* yp = sy[tok];

        // (1) corr numerators, sliding float4 window.
        //     lane owns shifts s = 4*lane + r + 128*sub  (r = 0..3)
        float a0 = 0.f, a1 = 0.f, a2 = 0.f, a3 = 0.f;
        {
            const float4* xv = (const float4*)(xp) + lane + 32 * sub;  // chunk base s/4
            const float4* yv = (const float4*)(yp);
            float4 cur = xv[0];
            #pragma unroll 8
            for (int t = 0; t < 32; t++) {
                float4 nxt = xv[t + 1];
                float4 y4  = yv[t];
                a0 = fmaf(cur.x, y4.x, a0); a0 = fmaf(cur.y, y4.y, a0);
                a0 = fmaf(cur.z, y4.z, a0); a0 = fmaf(cur.w, y4.w, a0);
                a1 = fmaf(cur.y, y4.x, a1); a1 = fmaf(cur.z, y4.y, a1);
                a1 = fmaf(cur.w, y4.z, a1); a1 = fmaf(nxt.x, y4.w, a1);
                a2 = fmaf(cur.z, y4.x, a2); a2 = fmaf(cur.w, y4.y, a2);
                a2 = fmaf(nxt.x, y4.z, a2); a2 = fmaf(nxt.y, y4.w, a2);
                a3 = fmaf(cur.w, y4.x, a3); a3 = fmaf(nxt.x, y4.y, a3);
                a3 = fmaf(nxt.y, y4.z, a3); a3 = fmaf(nxt.z, y4.w, a3);
                cur = nxt;
            }
        }

        // (2) per-warp sim + first-max argmax over its 128 shifts
        {
            const int s0 = 4 * lane + 128 * sub;
            float num[4] = {a0, a1, a2, a3};
            float bv = -INFINITY; int bi = 0;
            #pragma unroll
            for (int r = 0; r < 4; r++) {
                int s = s0 + r;
                float sim;
                if (s < 255) {
                    int lo = s - 127; if (lo < 0) lo = 0;
                    int hi = s;       if (hi > 127) hi = 127;
                    float dxv = Pp[hi + 1] - Pp[lo];
                    sim = (dxv > 0.f) ? num[r] * rsqrtf(dxv) : 0.f;
                } else sim = -INFINITY;
                if (sim > bv) { bv = sim; bi = s; }   // ascending s keeps first max
            }
            #pragma unroll
            for (int o = 16; o > 0; o >>= 1) {
                float ov = __shfl_xor_sync(FULLMASK, bv, o);
                int   oi = __shfl_xor_sync(FULLMASK, bi, o);
                if (ov > bv || (ov == bv && oi < bi)) { bv = ov; bi = oi; }
            }
            if (lane == 0) { s_bv[tok][sub] = bv; s_bi[tok][sub] = bi; }
        }
        PAIR_BAR(tok);     // pair-local: per-warp bests visible

        // (3) BOTH warps: combine, softmax attention, x_attn (redundant identical)
        int bi;
        {
            float v0 = s_bv[tok][0]; int i0 = s_bi[tok][0];
            float v1 = s_bv[tok][1]; int i1 = s_bi[tok][1];
            bi = (v1 > v0 || (v1 == v0 && i1 < i0)) ? i1 : i0;

            float xa[4], e[4];
            float m = -INFINITY;
            #pragma unroll
            for (int k = 0; k < 4; k++) {
                int d = k * 32 + lane;
                xa[k] = xp[bi + d];                    // kpt[bi][d]
                e[k]  = xa[k] * yp[d];
                m = fmaxf(m, e[k]);
            }
            #pragma unroll
            for (int o = 16; o > 0; o >>= 1) m = fmaxf(m, __shfl_xor_sync(FULLMASK, m, o));
            float se = 0.f;
            #pragma unroll
            for (int k = 0; k < 4; k++) { e[k] = __expf(e[k] - m); se += e[k]; }
            #pragma unroll
            for (int o = 16; o > 0; o >>= 1) se += __shfl_xor_sync(FULLMASK, se, o);
            float inv = 1.f / se;
            #pragma unroll
            for (int k = 0; k < 4; k++) {
                int d = k * 32 + lane;
                sxa[tok][d] = xa[k] * (e[k] * inv);    // both warps write same values
            }
        }
        __syncwarp();       // own sxa writes visible to own cross-lane reads

        // (4) x_res update (reads own-warp sxa copies)
        {
            const int off = bi - 127;
            #pragma unroll
            for (int k = 0; k < 4; k++) {
                int d = k * 32 + lane;
                int q = d - off;
                float xe = (q >= 0 && q < 128) ? sxa[tok][q] : 0.f;
                xr[k] -= xe;
            }
        }
        PAIR_BAR(tok);      // pair-local: xp softmax-reads done before republish

        // (5) republish xp (sub1) + prefix scan (sub0) for NEXT iteration
        if (sub == 1) {
            #pragma unroll
            for (int k = 0; k < 4; k++) xp[127 + k * 32 + lane] = xr[k];
        } else {
            float run = 0.f;
            #pragma unroll
            for (int k = 0; k < 4; k++) {
                float v = xr[k] * xr[k];
                #pragma unroll
                for (int o = 1; o < 32; o <<= 1) {
                    float n = __shfl_up_sync(FULLMASK, v, o);
                    if (lane >= o) v += n;
                }
                Pp[1 + k * 32 + lane] = run + v;
                run += __shfl_sync(FULLMASK, v, 31);
            }
            if (lane == 0) Pp[0] = 0.f;
        }
        __syncthreads();   // BAR-A: sxa visible for fused MLP

        // (6) fused MLP (half-d per thread) + loss + y_res update
        //     y_ele[g][o] = sum_d sxa[g][d] * Wf[it][d][o] + bf[it][o]
        {
            const float*  wp  = g_wf + (it * IDIM + m2_hf * 64) * IDIM + m2_oc * 4;
            const float4* hpv = (const float4*)(&sxa[m2_g][m2_hf * 64]);
            float c0 = 0.f, c1 = 0.f, c2 = 0.f, c3 = 0.f;
            #pragma unroll 4
            for (int k4 = 0; k4 < 16; k4++) {
                float4 h  = hpv[k4];
                const float* w = wp + (k4 * 4) * IDIM;
                float4 w0 = *(const float4*)(w);
                float4 w1v = *(const float4*)(w + IDIM);
                float4 w2v = *(const float4*)(w + 2 * IDIM);
                float4 w3v = *(const float4*)(w + 3 * IDIM);
                c0 = fmaf(w0.x, h.x, c0); c1 = fmaf(w0.y, h.x, c1);
                c2 = fmaf(w0.z, h.x, c2); c3 = fmaf(w0.w, h.x, c3);
                c0 = fmaf(w1v.x, h.y, c0); c1 = fmaf(w1v.y, h.y, c1);
                c2 = fmaf(w1v.z, h.y, c2); c3 = fmaf(w1v.w, h.y, c3);
                c0 = fmaf(w2v.x, h.z, c0); c1 = fmaf(w2v.y, h.z, c1);
                c2 = fmaf(w2v.z, h.z, c2); c3 = fmaf(w2v.w, h.z, c3);
                c0 = fmaf(w3v.x, h.w, c0); c1 = fmaf(w3v.y, h.w, c1);
                c2 = fmaf(w3v.z, h.w, c2); c3 = fmaf(w3v.w, h.w, c3);
            }
            // hoist pre-barrier operands for the epilogue
            float4 bfv = *(const float4*)(g_bf + it * IDIM + m2_oc * 4);
            float4 yr = *(const float4*)&sy[m2_g][m2_oc * 4];
            const unsigned char* mp = &smsk[m2_g][m2_oc * 4];
            unsigned char mk0 = mp[0], mk1 = mp[1], mk2 = mp[2], mk3 = mp[3];
            if (m2_hf == 1)
                *(float4*)&sye[m2_g][m2_oc * 4] = make_float4(c0, c1, c2, c3);
            __syncthreads();   // BAR-C: partials visible
            if (m2_hf == 0) {
                float4 pb = *(const float4*)&sye[m2_g][m2_oc * 4];
                float ye0 = c0 + pb.x + bfv.x;
                float ye1 = c1 + pb.y + bfv.y;
                float ye2 = c2 + pb.z + bfv.z;
                float ye3 = c3 + pb.w + bfv.w;
                float d0 = ye0 - yr.x, d1 = ye1 - yr.y, d2 = ye2 - yr.z, d3 = ye3 - yr.w;
                if (!mk0) lossAcc += d0 * d0;
                if (!mk1) lossAcc += d1 * d1;
                if (!mk2) lossAcc += d2 * d2;
                if (!mk3) lossAcc += d3 * d3;
                *(float4*)&sy[m2_g][m2_oc * 4] =
                    make_float4(yr.x - ye0, yr.y - ye1, yr.z - ye2, yr.w - ye3);
            }
        }
        // loop-top BAR-TOP orders the sy writes before next-iter corr reads
    }

    // ---- deterministic per-block loss reduction ----
    for (int o = 16; o > 0; o >>= 1) lossAcc += __shfl_xor_sync(FULLMASK, lossAcc, o);
    __syncthreads();                 // protect redf reuse
    if (lane == 0) redf[wid] = lossAcc;
    __syncthreads();
    if (tid == 0) {
        float s = 0.f;
        for (int w = 0; w < 8; w++) s += redf[w];
        g_partS[blk] = s;
        __threadfence();
        unsigned int t = atomicAdd(&g_ticket, 1u);
        sIsLast = (t == NBLK - 1) ? 1 : 0;
    }
    __syncthreads();

    // ---- last block: fused deterministic finalize ----
    if (sIsLast) {
        __threadfence();
        volatile float* vS = g_partS;
        volatile int*   vC = g_partC;
        float s = vS[tid] + vS[tid + 256];      // NBLK = 512 = 2*NT
        int   c = vC[tid] + vC[tid + 256];
        for (int o = 16; o > 0; o >>= 1) {
            s += __shfl_xor_sync(FULLMASK, s, o);
            c += __shfl_xor_sync(FULLMASK, c, o);
        }
        if (lane == 0) { redf[wid] = s; redi[wid] = c; }
        __syncthreads();
        if (tid == 0) {
            float S = 0.f; int C = 0;
            for (int w = 0; w < 8; w++) { S += redf[w]; C += redi[w]; }
            out[0] = S / (4.0f * (float)C);   // mean over NIT of (sum_sq / denom)
            g_ticket = 0;                     // reset for next graph replay
        }
    }
}

extern "C" void kernel_launch(void* const* d_in, const int* in_sizes, int n_in,
                              void* d_out, int out_size)
{
    const float* x  = (const float*)d_in[0];
    const float* y  = (const float*)d_in[1];
    const float* w1 = (const float*)d_in[2];
    const float* b1 = (const float*)d_in[3];
    const float* w2 = (const float*)d_in[4];
    const float* b2 = (const float*)d_in[5];

    gemm_fuse<<<64, dim3(32, 8)>>>(w1, w2, b1, b2);
    fwd_kernel<<<NBLK, NT>>>(x, y, (float*)d_out);
}

// round 13
// speedup vs baseline: 2.0835x; 1.0680x over previous
#include <cuda_runtime.h>
#include <math.h>

#define IDIM 128
#define HDIM 1024
#define CDIM 256
#define NIT  4
#define NTOK 2048
#define G    4            // tokens per block (two warps per token)
#define NT   256          // threads per block
#define NBLK (NTOK / G)   // 512 blocks
#define IGNORE_OUT 10000.0f
#define FULLMASK 0xffffffffu

// pair-local named barriers (64 threads each)
// corr pairs: warps (2t, 2t+1), ids 1..4
#define PAIR_BAR(tokid) asm volatile("bar.sync %0, 64;" :: "r"((tokid) + 1) : "memory")
// MLP pairs: warps (t, t+4), ids 5..8
#define MLP_BAR(tokid)  asm volatile("bar.sync %0, 64;" :: "r"((tokid) + 5) : "memory")

// ---- device scratch (no allocations allowed) ----
__device__ float g_wf[NIT * IDIM * IDIM];  // fused W: [it][d][o], o-contiguous
__device__ float g_bf[NIT * IDIM];         // fused bias: [it][o]
__device__ float g_partS[NBLK];
__device__ int   g_partC[NBLK];
__device__ unsigned int g_ticket;          // zero-init; reset by last block each replay

// ================= prologue: fused-weight GEMM =================
// Wf[it][d][o] = sum_{c<256} w1[it*256+c][d] * w2[o][it*256+c]
// bf[it][o]    = sum_{c<256} b1[it*256+c]    * w2[o][it*256+c] + b2[o]
__global__ __launch_bounds__(256) void gemm_fuse(const float* __restrict__ w1,
                                                 const float* __restrict__ w2,
                                                 const float* __restrict__ b1,
                                                 const float* __restrict__ b2)
{
    __shared__ float As[32][33];   // [c][d_local]
    __shared__ float Bs[32][33];   // [c][o_local]
    const int b  = blockIdx.x;     // 64 blocks: it(4) x dt(4) x ot(4)
    const int it = b >> 4;
    const int dt = (b >> 2) & 3;
    const int ot = b & 3;
    const int tx = threadIdx.x;    // 0..31 (o_local / col)
    const int ty = threadIdx.y;    // 0..7

    float acc[4] = {0.f, 0.f, 0.f, 0.f};
    float bacc = 0.f;

    for (int kc = 0; kc < 8; kc++) {
        #pragma unroll
        for (int i = 0; i < 4; i++) {
            int c = ty + 8 * i;
            As[c][tx] = w1[(it * CDIM + kc * 32 + c) * IDIM + dt * 32 + tx];
            Bs[tx][c] = w2[(ot * 32 + c) * HDIM + it * CDIM + kc * 32 + tx];
        }
        __syncthreads();
        #pragma unroll 8
        for (int c = 0; c < 32; c++) {
            float bv = Bs[c][tx];
            #pragma unroll
            for (int i = 0; i < 4; i++)
                acc[i] = fmaf(As[c][ty + 8 * i], bv, acc[i]);
        }
        if (dt == 0 && ty == 0) {
            #pragma unroll 8
            for (int c = 0; c < 32; c++)
                bacc = fmaf(b1[it * CDIM + kc * 32 + c], Bs[c][tx], bacc);
        }
        __syncthreads();
    }
    #pragma unroll
    for (int i = 0; i < 4; i++)
        g_wf[(it * IDIM + dt * 32 + ty + 8 * i) * IDIM + ot * 32 + tx] = acc[i];
    if (dt == 0 && ty == 0)
        g_bf[it * IDIM + ot * 32 + tx] = bacc + b2[ot * 32 + tx];
}

// ================= fused forward =================
__global__ __launch_bounds__(NT, 4)
void fwd_kernel(const float* __restrict__ x,  const float* __restrict__ y,
                float* __restrict__ out)
{
    __shared__ __align__(16) float sxp[G][384];       // zero-padded x_res (pad 127 each side)
    __shared__ __align__(16) float sy [G][132];       // y_res (padded)
    __shared__ __align__(16) float sxa[G][132];       // x_attn (padded)
    __shared__ __align__(16) float sP [G][132];       // prefix sums of x^2 (129 used)
    __shared__ __align__(16) float sye[G][132];       // fused-MLP half-1 partials
    __shared__ float s_bv[G][2];                      // per-warp argmax value
    __shared__ int   s_bi[G][2];                      // per-warp argmax index
    __shared__ unsigned char smsk[G][128];            // seq_mask from ORIGINAL y
    __shared__ float redf[8];
    __shared__ int   redi[8];
    __shared__ int   sIsLast;

    const int tid  = threadIdx.x;
    const int blk  = blockIdx.x;
    const int tok0 = blk * G;
    const int lane = tid & 31;
    const int wid  = tid >> 5;        // 8 warps
    const int tok  = wid >> 1;        // token for per-token (corr) phases
    const int sub  = wid & 1;         // corr pass: s in [128*sub, 128*sub+128)

    // ---- zero sxp pads + load y/mask + count ----
    for (int k = tid; k < G * 384; k += NT) sxp[k / 384][k % 384] = 0.f;

    int cnt = 0;
    #pragma unroll
    for (int q = 0; q < 2; q++) {
        int k = tid + q * NT;                 // 0..511 over (g,d)
        int g = k >> 7, d = k & 127;
        float yv = y[(tok0 + g) * IDIM + d];
        sy[g][d] = yv;
        unsigned char m = (yv == IGNORE_OUT) ? 1 : 0;
        smsk[g][d] = m;
        cnt += 1 - (int)m;
    }
    for (int o = 16; o > 0; o >>= 1) cnt += __shfl_xor_sync(FULLMASK, cnt, o);
    if (lane == 0) redi[wid] = cnt;

    // x_res registers: BOTH warps of a token pair hold identical copies.
    float xr[4];
    #pragma unroll
    for (int k = 0; k < 4; k++)
        xr[k] = x[(tok0 + tok) * IDIM + k * 32 + lane];

    __syncthreads();
    if (tid == 0) {
        int c = 0;
        for (int w = 0; w < 8; w++) c += redi[w];
        g_partC[blk] = c;
    }

    // fused-MLP mapping: token constant per warp (conflict-free LDS)
    const int m2_tok = wid & 3;            // token
    const int m2_hf  = wid >> 2;           // d half (warps w and w+4 pair up)

    // ---- prologue: publish xp + prefix sums for iteration 0 ----
    {
        float* xp = sxp[tok];
        float* Pp = sP[tok];
        if (sub == 1) {
            #pragma unroll
            for (int k = 0; k < 4; k++) xp[127 + k * 32 + lane] = xr[k];
        } else {
            float run = 0.f;
            #pragma unroll
            for (int k = 0; k < 4; k++) {
                float v = xr[k] * xr[k];
                #pragma unroll
                for (int o = 1; o < 32; o <<= 1) {
                    float n = __shfl_up_sync(FULLMASK, v, o);
                    if (lane >= o) v += n;
                }
                Pp[1 + k * 32 + lane] = run + v;
                run += __shfl_sync(FULLMASK, v, 31);
            }
            if (lane == 0) Pp[0] = 0.f;
        }
    }

    float lossAcc = 0.f;

    for (int it = 0; it < NIT; ++it) {
        __syncthreads();   // BAR-TOP: xp/sP publish + prev-iter sy visible

        float* xp = sxp[tok];
        float* Pp = sP[tok];
        float* yp = sy[tok];

        // (1) corr numerators, sliding float4 window.
        //     lane owns shifts s = 4*lane + r + 128*sub  (r = 0..3)
        float a0 = 0.f, a1 = 0.f, a2 = 0.f, a3 = 0.f;
        {
            const float4* xv = (const float4*)(xp) + lane + 32 * sub;  // chunk base s/4
            const float4* yv = (const float4*)(yp);
            float4 cur = xv[0];
            #pragma unroll 8
            for (int t = 0; t < 32; t++) {
                float4 nxt = xv[t + 1];
                float4 y4  = yv[t];
                a0 = fmaf(cur.x, y4.x, a0); a0 = fmaf(cur.y, y4.y, a0);
                a0 = fmaf(cur.z, y4.z, a0); a0 = fmaf(cur.w, y4.w, a0);
                a1 = fmaf(cur.y, y4.x, a1); a1 = fmaf(cur.z, y4.y, a1);
                a1 = fmaf(cur.w, y4.z, a1); a1 = fmaf(nxt.x, y4.w, a1);
                a2 = fmaf(cur.z, y4.x, a2); a2 = fmaf(cur.w, y4.y, a2);
                a2 = fmaf(nxt.x, y4.z, a2); a2 = fmaf(nxt.y, y4.w, a2);
                a3 = fmaf(cur.w, y4.x, a3); a3 = fmaf(nxt.x, y4.y, a3);
                a3 = fmaf(nxt.y, y4.z, a3); a3 = fmaf(nxt.z, y4.w, a3);
                cur = nxt;
            }
        }

        // (2) per-warp sim + first-max argmax over its 128 shifts
        {
            const int s0 = 4 * lane + 128 * sub;
            float num[4] = {a0, a1, a2, a3};
            float bv = -INFINITY; int bi = 0;
            #pragma unroll
            for (int r = 0; r < 4; r++) {
                int s = s0 + r;
                float sim;
                if (s < 255) {
                    int lo = s - 127; if (lo < 0) lo = 0;
                    int hi = s;       if (hi > 127) hi = 127;
                    float dxv = Pp[hi + 1] - Pp[lo];
                    sim = (dxv > 0.f) ? num[r] * rsqrtf(dxv) : 0.f;
                } else sim = -INFINITY;
                if (sim > bv) { bv = sim; bi = s; }   // ascending s keeps first max
            }
            #pragma unroll
            for (int o = 16; o > 0; o >>= 1) {
                float ov = __shfl_xor_sync(FULLMASK, bv, o);
                int   oi = __shfl_xor_sync(FULLMASK, bi, o);
                if (ov > bv || (ov == bv && oi < bi)) { bv = ov; bi = oi; }
            }
            if (lane == 0) { s_bv[tok][sub] = bv; s_bi[tok][sub] = bi; }
        }
        PAIR_BAR(tok);     // pair-local: per-warp bests visible

        // (3) BOTH warps: combine, softmax attention, x_attn (redundant identical)
        int bi;
        {
            float v0 = s_bv[tok][0]; int i0 = s_bi[tok][0];
            float v1 = s_bv[tok][1]; int i1 = s_bi[tok][1];
            bi = (v1 > v0 || (v1 == v0 && i1 < i0)) ? i1 : i0;

            float xa[4], e[4];
            float m = -INFINITY;
            #pragma unroll
            for (int k = 0; k < 4; k++) {
                int d = k * 32 + lane;
                xa[k] = xp[bi + d];                    // kpt[bi][d]
                e[k]  = xa[k] * yp[d];
                m = fmaxf(m, e[k]);
            }
            #pragma unroll
            for (int o = 16; o > 0; o >>= 1) m = fmaxf(m, __shfl_xor_sync(FULLMASK, m, o));
            float se = 0.f;
            #pragma unroll
            for (int k = 0; k < 4; k++) { e[k] = __expf(e[k] - m); se += e[k]; }
            #pragma unroll
            for (int o = 16; o > 0; o >>= 1) se += __shfl_xor_sync(FULLMASK, se, o);
            float inv = 1.f / se;
            #pragma unroll
            for (int k = 0; k < 4; k++) {
                int d = k * 32 + lane;
                sxa[tok][d] = xa[k] * (e[k] * inv);    // both warps write same values
            }
        }
        __syncwarp();       // own sxa writes visible to own cross-lane reads

        // (4) x_res update (reads own-warp sxa copies)
        {
            const int off = bi - 127;
            #pragma unroll
            for (int k = 0; k < 4; k++) {
                int d = k * 32 + lane;
                int q = d - off;
                float xe = (q >= 0 && q < 128) ? sxa[tok][q] : 0.f;
                xr[k] -= xe;
            }
        }
        PAIR_BAR(tok);      // pair-local: xp softmax-reads done before republish

        // (5) republish xp (sub1) + prefix scan (sub0) for NEXT iteration
        if (sub == 1) {
            #pragma unroll
            for (int k = 0; k < 4; k++) xp[127 + k * 32 + lane] = xr[k];
        } else {
            float run = 0.f;
            #pragma unroll
            for (int k = 0; k < 4; k++) {
                float v = xr[k] * xr[k];
                #pragma unroll
                for (int o = 1; o < 32; o <<= 1) {
                    float n = __shfl_up_sync(FULLMASK, v, o);
                    if (lane >= o) v += n;
                }
                Pp[1 + k * 32 + lane] = run + v;
                run += __shfl_sync(FULLMASK, v, 31);
            }
            if (lane == 0) Pp[0] = 0.f;
        }
        __syncthreads();   // BAR-A: sxa visible for fused MLP

        // (6) fused MLP: token per warp (broadcast activations, coalesced weights)
        //     warp w handles token w&3, d-half w>>2; lane owns outputs lane*4..+3
        {
            const float*  wp  = g_wf + (it * IDIM + m2_hf * 64) * IDIM + lane * 4;
            const float4* hpv = (const float4*)(&sxa[m2_tok][m2_hf * 64]);
            float c0 = 0.f, c1 = 0.f, c2 = 0.f, c3 = 0.f;
            #pragma unroll 4
            for (int k4 = 0; k4 < 16; k4++) {
                float4 h  = hpv[k4];                   // broadcast (1 address/warp)
                const float* w = wp + (k4 * 4) * IDIM;
                float4 w0 = *(const float4*)(w);
                float4 w1v = *(const float4*)(w + IDIM);
                float4 w2v = *(const float4*)(w + 2 * IDIM);
                float4 w3v = *(const float4*)(w + 3 * IDIM);
                c0 = fmaf(w0.x, h.x, c0); c1 = fmaf(w0.y, h.x, c1);
                c2 = fmaf(w0.z, h.x, c2); c3 = fmaf(w0.w, h.x, c3);
                c0 = fmaf(w1v.x, h.y, c0); c1 = fmaf(w1v.y, h.y, c1);
                c2 = fmaf(w1v.z, h.y, c2); c3 = fmaf(w1v.w, h.y, c3);
                c0 = fmaf(w2v.x, h.z, c0); c1 = fmaf(w2v.y, h.z, c1);
                c2 = fmaf(w2v.z, h.z, c2); c3 = fmaf(w2v.w, h.z, c3);
                c0 = fmaf(w3v.x, h.w, c0); c1 = fmaf(w3v.y, h.w, c1);
                c2 = fmaf(w3v.z, h.w, c2); c3 = fmaf(w3v.w, h.w, c3);
            }
            if (m2_hf == 1)
                *(float4*)&sye[m2_tok][lane * 4] = make_float4(c0, c1, c2, c3);
            MLP_BAR(m2_tok);   // pair-local (w, w+4): partials visible
            if (m2_hf == 0) {
                float4 pb  = *(const float4*)&sye[m2_tok][lane * 4];
                float4 bfv = *(const float4*)(g_bf + it * IDIM + lane * 4);
                float4 yr  = *(const float4*)&sy[m2_tok][lane * 4];
                unsigned int mw = *(const unsigned int*)&smsk[m2_tok][lane * 4];
                float ye0 = c0 + pb.x + bfv.x;
                float ye1 = c1 + pb.y + bfv.y;
                float ye2 = c2 + pb.z + bfv.z;
                float ye3 = c3 + pb.w + bfv.w;
                float d0 = ye0 - yr.x, d1 = ye1 - yr.y, d2 = ye2 - yr.z, d3 = ye3 - yr.w;
                float k0 = (mw & 0x000000ffu) ? 0.f : 1.f;
                float k1 = (mw & 0x0000ff00u) ? 0.f : 1.f;
                float k2 = (mw & 0x00ff0000u) ? 0.f : 1.f;
                float k3 = (mw & 0xff000000u) ? 0.f : 1.f;
                lossAcc = fmaf(k0 * d0, d0, lossAcc);
                lossAcc = fmaf(k1 * d1, d1, lossAcc);
                lossAcc = fmaf(k2 * d2, d2, lossAcc);
                lossAcc = fmaf(k3 * d3, d3, lossAcc);
                *(float4*)&sy[m2_tok][lane * 4] =
                    make_float4(yr.x - ye0, yr.y - ye1, yr.z - ye2, yr.w - ye3);
            }
        }
        // loop-top BAR-TOP orders the sy writes before next-iter corr reads
    }

    // ---- deterministic per-block loss reduction ----
    for (int o = 16; o > 0; o >>= 1) lossAcc += __shfl_xor_sync(FULLMASK, lossAcc, o);
    __syncthreads();                 // protect redf reuse
    if (lane == 0) redf[wid] = lossAcc;
    __syncthreads();
    if (tid == 0) {
        float s = 0.f;
        for (int w = 0; w < 8; w++) s += redf[w];
        g_partS[blk] = s;
        __threadfence();
        unsigned int t = atomicAdd(&g_ticket, 1u);
        sIsLast = (t == NBLK - 1) ? 1 : 0;
    }
    __syncthreads();

    // ---- last block: fused deterministic finalize ----
    if (sIsLast) {
        __threadfence();
        volatile float* vS = g_partS;
        volatile int*   vC = g_partC;
        float s = vS[tid] + vS[tid + 256];      // NBLK = 512 = 2*NT
        int   c = vC[tid] + vC[tid + 256];
        for (int o = 16; o > 0; o >>= 1) {
            s += __shfl_xor_sync(FULLMASK, s, o);
            c += __shfl_xor_sync(FULLMASK, c, o);
        }
        if (lane == 0) { redf[wid] = s; redi[wid] = c; }
        __syncthreads();
        if (tid == 0) {
            float S = 0.f; int C = 0;
            for (int w = 0; w < 8; w++) { S += redf[w]; C += redi[w]; }
            out[0] = S / (4.0f * (float)C);   // mean over NIT of (sum_sq / denom)
            g_ticket = 0;                     // reset for next graph replay
        }
    }
}

extern "C" void kernel_launch(void* const* d_in, const int* in_sizes, int n_in,
                              void* d_out, int out_size)
{
    const float* x  = (const float*)d_in[0];
    const float* y  = (const float*)d_in[1];
    const float* w1 = (const float*)d_in[2];
    const float* b1 = (const float*)d_in[3];
    const float* w2 = (const float*)d_in[4];
    const float* b2 = (const float*)d_in[5];

    gemm_fuse<<<64, dim3(32, 8)>>>(w1, w2, b1, b2);
    fwd_kernel<<<NBLK, NT>>>(x, y, (float*)d_out);
}